// round 11
// baseline (speedup 1.0000x reference)
#include <cuda_runtime.h>
#include <cstdint>

// ReprojectionLayer: out[b,j,x,y,z] = mean_c heatmaps[b,c,j, v*512+u]
//   (u,v) = reproLookup[c, sx+x, sy+y, sz+z, :], s* = clamp(trunc((center+160)/2)-52, 0, L-G)
//
// Strategy (r11):
//   Pass 1: register-only transpose+quantize fp32 -> u8 rows T[B,C,HW], 23
//           joints padded to 32B (one sector per row). Launched PER BATCH.
//   Pass 2: gather per batch (12 u8 planes = 101MB, L2-resident), pair-lane
//           row fetch + u16 SIMD accumulate (r10).
//   NEW: stream overlap. T(b1) runs on an aux stream concurrently with
//        gather(b0); gather(b1) joins via event. T(b0)->gather(b0) adjacency
//        also leaves T(b0) warm in L2.
// Precision: u8 quantization -> rel_err ~6.4e-4 < 1e-3 (measured r8-r10).

#define NB 2
#define NC 12
#define NJ 23
#define GG 104
#define HALFG 52
#define LL 160
#define HMW 512
#define HW (512 * 512)
#define G3 (GG * GG * GG)   // 1,124,864 = 4394 * 256, warps always full

// Scratch: 2*12*262144 rows * 32B = 151 MB (2 uint4 per row)
__device__ uint4 g_T[(size_t)NB * NC * HW * 2];

// ---------------- Pass 1: transpose + fp32 -> u8 (register-only) ----------------
// grid = (HW/1024, NC), block = 256; one launch per batch.
__global__ __launch_bounds__(256) void transpose_kernel(const float* __restrict__ hm, int b)
{
    const int c = blockIdx.y;
    const int p = blockIdx.x * 1024 + threadIdx.x * 4;

    const float4* src = reinterpret_cast<const float4*>(
        hm + ((size_t)(b * NC + c) * NJ) * HW + p);

    uint32_t w[4][6];
#pragma unroll
    for (int k = 0; k < 4; ++k)
#pragma unroll
        for (int i = 0; i < 6; ++i) w[k][i] = 0;

#pragma unroll
    for (int j = 0; j < NJ; ++j) {
        const float4 f = __ldg(src + (size_t)j * (HW / 4));
        const int word = j >> 2, sh = 8 * (j & 3);
        w[0][word] |= __float2uint_rn(f.x * 255.0f) << sh;
        w[1][word] |= __float2uint_rn(f.y * 255.0f) << sh;
        w[2][word] |= __float2uint_rn(f.z * 255.0f) << sh;
        w[3][word] |= __float2uint_rn(f.w * 255.0f) << sh;
    }

    uint4* dst = g_T + ((size_t)(b * NC + c) * HW + p) * 2;
#pragma unroll
    for (int k = 0; k < 4; ++k) {
        dst[2 * k]     = make_uint4(w[k][0], w[k][1], w[k][2], w[k][3]);
        dst[2 * k + 1] = make_uint4(w[k][4], w[k][5], 0u, 0u);
    }
}

// ---------------- Pass 2: gather, pair-lane row fetch (r10) ----------------
__global__ __launch_bounds__(256) void gather_kernel(
    const float* __restrict__ center,
    const int2* __restrict__ lookup,
    float* __restrict__ out,
    int b)
{
    const int lane = threadIdx.x & 31;
    const int vox = blockIdx.x * blockDim.x + threadIdx.x;   // grid covers G3 exactly

    const int z = vox % GG;
    const int t = vox / GG;
    const int y = t % GG;
    const int x = t / GG;

    int sx = (int)((center[b * 3 + 0] + 160.0f) * 0.5f) - HALFG;
    int sy = (int)((center[b * 3 + 1] + 160.0f) * 0.5f) - HALFG;
    int sz = (int)((center[b * 3 + 2] + 160.0f) * 0.5f) - HALFG;
    sx = min(max(sx, 0), LL - GG);
    sy = min(max(sy, 0), LL - GG);
    sz = min(max(sz, 0), LL - GG);

    const int lx = sx + x, ly = sy + y, lz = sz + z;

    int base2[NC];
#pragma unroll
    for (int c = 0; c < NC; ++c) {
        const int lidx = ((c * LL + lx) * LL + ly) * LL + lz;
        const int2 uv = __ldg(&lookup[lidx]);
        base2[c] = ((b * NC + c) * HW + (uv.y * HMW + uv.x)) * 2;
    }

    uint32_t accLo[2][4] = {{0,0,0,0},{0,0,0,0}};
    uint32_t accHi[2][4] = {{0,0,0,0},{0,0,0,0}};
    const int srcRow = lane >> 1;
    const int part = lane & 1;

#pragma unroll
    for (int c = 0; c < NC; ++c) {
#pragma unroll
        for (int h = 0; h < 2; ++h) {
            const int rowbase = __shfl_sync(0xffffffffu, base2[c], (h << 4) + srcRow);
            const uint4 q = __ldg(&g_T[rowbase + part]);   // pair lanes share one sector
            accLo[h][0] += q.x & 0x00FF00FFu;  accHi[h][0] += (q.x >> 8) & 0x00FF00FFu;
            accLo[h][1] += q.y & 0x00FF00FFu;  accHi[h][1] += (q.y >> 8) & 0x00FF00FFu;
            accLo[h][2] += q.z & 0x00FF00FFu;  accHi[h][2] += (q.z >> 8) & 0x00FF00FFu;
            accLo[h][3] += q.w & 0x00FF00FFu;  accHi[h][3] += (q.w >> 8) & 0x00FF00FFu;
        }
    }

    const int k = lane & 15;
    const bool hi = lane >= 16;
    uint32_t eLo[4], eHi[4], oLo[2], oHi[2];
#pragma unroll
    for (int w = 0; w < 4; ++w) {
        const uint32_t a0 = __shfl_sync(0xffffffffu, accLo[0][w], 2 * k);
        const uint32_t a1 = __shfl_sync(0xffffffffu, accLo[1][w], 2 * k);
        eLo[w] = hi ? a1 : a0;
        const uint32_t b0 = __shfl_sync(0xffffffffu, accHi[0][w], 2 * k);
        const uint32_t b1 = __shfl_sync(0xffffffffu, accHi[1][w], 2 * k);
        eHi[w] = hi ? b1 : b0;
    }
#pragma unroll
    for (int w = 0; w < 2; ++w) {
        const uint32_t a0 = __shfl_sync(0xffffffffu, accLo[0][w], 2 * k + 1);
        const uint32_t a1 = __shfl_sync(0xffffffffu, accLo[1][w], 2 * k + 1);
        oLo[w] = hi ? a1 : a0;
        const uint32_t b0 = __shfl_sync(0xffffffffu, accHi[0][w], 2 * k + 1);
        const uint32_t b1 = __shfl_sync(0xffffffffu, accHi[1][w], 2 * k + 1);
        oHi[w] = hi ? b1 : b0;
    }

    const float scale = 1.0f / (12.0f * 255.0f);
    float* outb = out + ((size_t)b * NJ) * G3 + vox;
#pragma unroll
    for (int w = 0; w < 4; ++w) {          // joints 0..15
        const int j0 = 4 * w;
        outb[(size_t)(j0 + 0) * G3] = (float)(eLo[w] & 0xFFFFu) * scale;
        outb[(size_t)(j0 + 1) * G3] = (float)(eHi[w] & 0xFFFFu) * scale;
        outb[(size_t)(j0 + 2) * G3] = (float)(eLo[w] >> 16) * scale;
        outb[(size_t)(j0 + 3) * G3] = (float)(eHi[w] >> 16) * scale;
    }
#pragma unroll
    for (int w = 0; w < 2; ++w) {          // joints 16..23 (skip pad j23)
        const int j0 = 16 + 4 * w;
        outb[(size_t)(j0 + 0) * G3] = (float)(oLo[w] & 0xFFFFu) * scale;
        outb[(size_t)(j0 + 1) * G3] = (float)(oHi[w] & 0xFFFFu) * scale;
        outb[(size_t)(j0 + 2) * G3] = (float)(oLo[w] >> 16) * scale;
        if (j0 + 3 < NJ)
            outb[(size_t)(j0 + 3) * G3] = (float)(oHi[w] >> 16) * scale;
    }
}

extern "C" void kernel_launch(void* const* d_in, const int* in_sizes, int n_in,
                              void* d_out, int out_size)
{
    const float* heatmaps = (const float*)d_in[0];
    const float* center   = (const float*)d_in[1];
    const int2*  lookup   = (const int2*)d_in[2];
    float* out = (float*)d_out;

    // Created once on the first (uncaptured correctness) call; reused in capture.
    // No device-memory allocation involved.
    static cudaStream_t s_aux = []() {
        cudaStream_t s; cudaStreamCreateWithFlags(&s, cudaStreamNonBlocking); return s;
    }();
    static cudaEvent_t evT0 = []() {
        cudaEvent_t e; cudaEventCreateWithFlags(&e, cudaEventDisableTiming); return e;
    }();
    static cudaEvent_t evT1 = []() {
        cudaEvent_t e; cudaEventCreateWithFlags(&e, cudaEventDisableTiming); return e;
    }();

    const dim3 tgrid(HW / 1024, NC);
    const int nblk = G3 / 256;

    // main stream: T(b0) -> gather(b0)
    transpose_kernel<<<tgrid, 256>>>(heatmaps, 0);
    cudaEventRecord(evT0, 0);
    gather_kernel<<<nblk, 256>>>(center, lookup, out, 0);

    // aux stream: T(b1) overlapped with gather(b0)
    cudaStreamWaitEvent(s_aux, evT0, 0);
    transpose_kernel<<<tgrid, 256, 0, s_aux>>>(heatmaps, 1);
    cudaEventRecord(evT1, s_aux);

    // main stream: gather(b1) after T(b1)
    cudaStreamWaitEvent(0, evT1, 0);
    gather_kernel<<<nblk, 256>>>(center, lookup, out, 1);
}

// round 12
// speedup vs baseline: 1.0804x; 1.0804x over previous
#include <cuda_runtime.h>
#include <cstdint>

// ReprojectionLayer: out[b,j,x,y,z] = mean_c heatmaps[b,c,j, v*512+u]
//   (u,v) = reproLookup[c, sx+x, sy+y, sz+z, :], s* = clamp(trunc((center+160)/2)-52, 0, L-G)
//
// Strategy (r12): total-DRAM-bytes minimization.
//   Pass 1: register-only transpose+quantize fp32 -> u8 rows T[B,C,HW], 23
//           joints padded to 32B (one sector per row).
//   Pass 2: FOUR gather passes, one per (batch, 6-cam half): per-pass T
//           working set = 50MB << L2, so random row gathers hit L2.
//           Half A writes packed u16 SIMD accumulators (48B/vox) to scratch;
//           half B adds, unpacks, scales, writes fp32 output.
//           Streaming cache hints (__ldcs/__stcs) on lookup/partial/output
//           keep L2 capacity reserved for T rows.
// Precision: u8 quantization -> rel_err ~6.4e-4 < 1e-3 (measured r8-r11).

#define NB 2
#define NC 12
#define NCP 6
#define NJ 23
#define GG 104
#define HALFG 52
#define LL 160
#define HMW 512
#define HW (512 * 512)
#define G3 (GG * GG * GG)   // 1,124,864 = 4394 * 256

// T: 2*12*262144 rows * 32B = 151 MB
__device__ uint4 g_T[(size_t)NB * NC * HW * 2];
// Partial sums: 12 u32 planes of G3 (u16-lane SIMD words) = 54 MB, reused per batch
__device__ uint32_t g_P[12 * (size_t)G3];

// ---------------- Pass 1: transpose + fp32 -> u8 (register-only, r9) ----------------
__global__ __launch_bounds__(256) void transpose_kernel(const float* __restrict__ hm)
{
    const int c = blockIdx.y, b = blockIdx.z;
    const int p = blockIdx.x * 1024 + threadIdx.x * 4;

    const float4* src = reinterpret_cast<const float4*>(
        hm + ((size_t)(b * NC + c) * NJ) * HW + p);

    uint32_t w[4][6];
#pragma unroll
    for (int k = 0; k < 4; ++k)
#pragma unroll
        for (int i = 0; i < 6; ++i) w[k][i] = 0;

#pragma unroll
    for (int j = 0; j < NJ; ++j) {
        const float4 f = __ldg(src + (size_t)j * (HW / 4));
        const int word = j >> 2, sh = 8 * (j & 3);
        w[0][word] |= __float2uint_rn(f.x * 255.0f) << sh;
        w[1][word] |= __float2uint_rn(f.y * 255.0f) << sh;
        w[2][word] |= __float2uint_rn(f.z * 255.0f) << sh;
        w[3][word] |= __float2uint_rn(f.w * 255.0f) << sh;
    }

    uint4* dst = g_T + ((size_t)(b * NC + c) * HW + p) * 2;
#pragma unroll
    for (int k = 0; k < 4; ++k) {
        dst[2 * k]     = make_uint4(w[k][0], w[k][1], w[k][2], w[k][3]);
        dst[2 * k + 1] = make_uint4(w[k][4], w[k][5], 0u, 0u);
    }
}

// ---------------- Pass 2: gather over 6 cams ----------------
// FINAL=0: write packed u16 partials to g_P (streaming stores).
// FINAL=1: add g_P, unpack, scale, write fp32 output (streaming stores).
template <int FINAL>
__global__ __launch_bounds__(256) void gather_pass(
    const float* __restrict__ center,
    const int2* __restrict__ lookup,
    float* __restrict__ out,
    int b, int cam0)
{
    const int vox = blockIdx.x * blockDim.x + threadIdx.x;   // grid covers G3 exactly

    const int z = vox % GG;
    const int t = vox / GG;
    const int y = t % GG;
    const int x = t / GG;

    int sx = (int)((center[b * 3 + 0] + 160.0f) * 0.5f) - HALFG;
    int sy = (int)((center[b * 3 + 1] + 160.0f) * 0.5f) - HALFG;
    int sz = (int)((center[b * 3 + 2] + 160.0f) * 0.5f) - HALFG;
    sx = min(max(sx, 0), LL - GG);
    sy = min(max(sy, 0), LL - GG);
    sz = min(max(sz, 0), LL - GG);

    const int lx = sx + x, ly = sy + y, lz = sz + z;

    int base2[NCP];
#pragma unroll
    for (int c = 0; c < NCP; ++c) {
        const int cc = cam0 + c;
        const int lidx = ((cc * LL + lx) * LL + ly) * LL + lz;
        const int2 uv = __ldcs(&lookup[lidx]);                 // streaming: no reuse
        base2[c] = ((b * NC + cc) * HW + (uv.y * HMW + uv.x)) * 2;
    }

    uint32_t accLo[6] = {0, 0, 0, 0, 0, 0};
    uint32_t accHi[6] = {0, 0, 0, 0, 0, 0};

#pragma unroll
    for (int c = 0; c < NCP; ++c) {
        const uint4 q0 = __ldg(&g_T[base2[c]]);                // reuse-bearing: keep in L2
        const uint2 q1 = __ldg(reinterpret_cast<const uint2*>(&g_T[base2[c] + 1]));
        const uint32_t w[6] = {q0.x, q0.y, q0.z, q0.w, q1.x, q1.y};
#pragma unroll
        for (int i = 0; i < 6; ++i) {
            accLo[i] += w[i] & 0x00FF00FFu;
            accHi[i] += (w[i] >> 8) & 0x00FF00FFu;
        }
    }

    if (!FINAL) {
#pragma unroll
        for (int i = 0; i < 6; ++i) {
            __stcs(&g_P[(size_t)i * G3 + vox], accLo[i]);
            __stcs(&g_P[(size_t)(i + 6) * G3 + vox], accHi[i]);
        }
    } else {
#pragma unroll
        for (int i = 0; i < 6; ++i) {
            accLo[i] += __ldcs(&g_P[(size_t)i * G3 + vox]);
            accHi[i] += __ldcs(&g_P[(size_t)(i + 6) * G3 + vox]);
        }
        const float scale = 1.0f / (12.0f * 255.0f);
        float* outb = out + ((size_t)b * NJ) * G3 + vox;
#pragma unroll
        for (int w = 0; w < 6; ++w) {
            const int j0 = 4 * w;
            __stcs(&outb[(size_t)(j0 + 0) * G3], (float)(accLo[w] & 0xFFFFu) * scale);
            if (j0 + 1 < NJ) __stcs(&outb[(size_t)(j0 + 1) * G3], (float)(accHi[w] & 0xFFFFu) * scale);
            if (j0 + 2 < NJ) __stcs(&outb[(size_t)(j0 + 2) * G3], (float)(accLo[w] >> 16) * scale);
            if (j0 + 3 < NJ) __stcs(&outb[(size_t)(j0 + 3) * G3], (float)(accHi[w] >> 16) * scale);
        }
    }
}

extern "C" void kernel_launch(void* const* d_in, const int* in_sizes, int n_in,
                              void* d_out, int out_size)
{
    const float* heatmaps = (const float*)d_in[0];
    const float* center   = (const float*)d_in[1];
    const int2*  lookup   = (const int2*)d_in[2];
    float* out = (float*)d_out;

    {
        dim3 grid(HW / 1024, NC, NB);
        transpose_kernel<<<grid, 256>>>(heatmaps);
    }
    const int nblk = G3 / 256;
    // Sequential passes: per-pass T working set = 6 planes (50MB) stays L2-resident.
    gather_pass<0><<<nblk, 256>>>(center, lookup, out, 0, 0);
    gather_pass<1><<<nblk, 256>>>(center, lookup, out, 0, NCP);
    gather_pass<0><<<nblk, 256>>>(center, lookup, out, 1, 0);
    gather_pass<1><<<nblk, 256>>>(center, lookup, out, 1, NCP);
}

// round 13
// speedup vs baseline: 1.1199x; 1.0366x over previous
#include <cuda_runtime.h>
#include <cstdint>

// ReprojectionLayer: out[b,j,x,y,z] = mean_c heatmaps[b,c,j, v*512+u]
//   (u,v) = reproLookup[c, sx+x, sy+y, sz+z, :], s* = clamp(trunc((center+160)/2)-52, 0, L-G)
//
// Strategy (r13):
//   Pass 1: register-only transpose+quantize fp32 -> u8 rows (one 32B sector
//           per row), streaming cache hints, launched per batch.
//   Pass 2: FOUR gather passes (batch x 6-cam half, 50MB L2-resident WS).
//           NEW: pair-lane row fetch (2 LDG.128/cam, ~16 lines each = 2x fewer
//           L1 wavefronts than uint4+uint2) + warp-shuffle reassembly; partials
//           packed u16 (48B/vox) with streaming hints.
//   NEW: T(b1) overlapped with gather(b0) passes on an aux stream (gathers now
//        run at 33% DRAM, leaving headroom for the DRAM-bound transpose).
// Precision: u8 quantization -> rel_err ~6.4e-4 < 1e-3 (measured r8-r12).

#define NB 2
#define NC 12
#define NCP 6
#define NJ 23
#define GG 104
#define HALFG 52
#define LL 160
#define HMW 512
#define HW (512 * 512)
#define G3 (GG * GG * GG)   // 1,124,864 = 4394 * 256

// T: 2*12*262144 rows * 32B = 151 MB
__device__ uint4 g_T[(size_t)NB * NC * HW * 2];
// Partial sums: 12 u32 planes (u16-lane SIMD words) = 54 MB, reused per batch
__device__ uint32_t g_P[12 * (size_t)G3];

// ---------------- Pass 1: transpose + fp32 -> u8 (register-only) ----------------
// grid = (HW/1024, NC), one launch per batch.
__global__ __launch_bounds__(256) void transpose_kernel(const float* __restrict__ hm, int b)
{
    const int c = blockIdx.y;
    const int p = blockIdx.x * 1024 + threadIdx.x * 4;

    const float4* src = reinterpret_cast<const float4*>(
        hm + ((size_t)(b * NC + c) * NJ) * HW + p);

    uint32_t w[4][6];
#pragma unroll
    for (int k = 0; k < 4; ++k)
#pragma unroll
        for (int i = 0; i < 6; ++i) w[k][i] = 0;

#pragma unroll
    for (int j = 0; j < NJ; ++j) {
        const float4 f = __ldcs(src + (size_t)j * (HW / 4));   // streaming read
        const int word = j >> 2, sh = 8 * (j & 3);
        w[0][word] |= __float2uint_rn(f.x * 255.0f) << sh;
        w[1][word] |= __float2uint_rn(f.y * 255.0f) << sh;
        w[2][word] |= __float2uint_rn(f.z * 255.0f) << sh;
        w[3][word] |= __float2uint_rn(f.w * 255.0f) << sh;
    }

    uint4* dst = g_T + ((size_t)(b * NC + c) * HW + p) * 2;
#pragma unroll
    for (int k = 0; k < 4; ++k) {
        __stcs(&dst[2 * k],     make_uint4(w[k][0], w[k][1], w[k][2], w[k][3]));
        __stcs(&dst[2 * k + 1], make_uint4(w[k][4], w[k][5], 0u, 0u));
    }
}

// ---------------- Pass 2: gather over 6 cams, pair-lane fetch ----------------
// FINAL=0: write packed u16 partials; FINAL=1: add partials, unpack, write fp32.
template <int FINAL>
__global__ __launch_bounds__(256) void gather_pass(
    const float* __restrict__ center,
    const int2* __restrict__ lookup,
    float* __restrict__ out,
    int b, int cam0)
{
    const int lane = threadIdx.x & 31;
    const int vox = blockIdx.x * blockDim.x + threadIdx.x;   // grid covers G3 exactly

    const int z = vox % GG;
    const int t = vox / GG;
    const int y = t % GG;
    const int x = t / GG;

    int sx = (int)((center[b * 3 + 0] + 160.0f) * 0.5f) - HALFG;
    int sy = (int)((center[b * 3 + 1] + 160.0f) * 0.5f) - HALFG;
    int sz = (int)((center[b * 3 + 2] + 160.0f) * 0.5f) - HALFG;
    sx = min(max(sx, 0), LL - GG);
    sy = min(max(sy, 0), LL - GG);
    sz = min(max(sz, 0), LL - GG);

    const int lx = sx + x, ly = sy + y, lz = sz + z;

    int base2[NCP];
#pragma unroll
    for (int c = 0; c < NCP; ++c) {
        const int cc = cam0 + c;
        const int lidx = ((cc * LL + lx) * LL + ly) * LL + lz;
        const int2 uv = __ldcs(&lookup[lidx]);                 // streaming: no reuse
        base2[c] = ((b * NC + cc) * HW + (uv.y * HMW + uv.x)) * 2;
    }

    // Pair-lane: lanes 2r,2r+1 fetch the two 16B halves of row r's 32B sector.
    uint32_t accLo[2][4] = {{0,0,0,0},{0,0,0,0}};
    uint32_t accHi[2][4] = {{0,0,0,0},{0,0,0,0}};
    const int srcRow = lane >> 1;
    const int part = lane & 1;

#pragma unroll
    for (int c = 0; c < NCP; ++c) {
#pragma unroll
        for (int h = 0; h < 2; ++h) {
            const int rowbase = __shfl_sync(0xffffffffu, base2[c], (h << 4) + srcRow);
            const uint4 q = __ldg(&g_T[rowbase + part]);       // reuse-bearing: cache in L2
            accLo[h][0] += q.x & 0x00FF00FFu;  accHi[h][0] += (q.x >> 8) & 0x00FF00FFu;
            accLo[h][1] += q.y & 0x00FF00FFu;  accHi[h][1] += (q.y >> 8) & 0x00FF00FFu;
            accLo[h][2] += q.z & 0x00FF00FFu;  accHi[h][2] += (q.z >> 8) & 0x00FF00FFu;
            accLo[h][3] += q.w & 0x00FF00FFu;  accHi[h][3] += (q.w >> 8) & 0x00FF00FFu;
        }
    }

    // Reassemble this voxel's 12 SIMD words (joints 0-15 from even source lane,
    // 16-23 from odd source lane).
    const int k = lane & 15;
    const bool hi = lane >= 16;
    uint32_t vLo[6], vHi[6];
#pragma unroll
    for (int w = 0; w < 4; ++w) {
        const uint32_t a0 = __shfl_sync(0xffffffffu, accLo[0][w], 2 * k);
        const uint32_t a1 = __shfl_sync(0xffffffffu, accLo[1][w], 2 * k);
        vLo[w] = hi ? a1 : a0;
        const uint32_t b0 = __shfl_sync(0xffffffffu, accHi[0][w], 2 * k);
        const uint32_t b1 = __shfl_sync(0xffffffffu, accHi[1][w], 2 * k);
        vHi[w] = hi ? b1 : b0;
    }
#pragma unroll
    for (int w = 0; w < 2; ++w) {
        const uint32_t a0 = __shfl_sync(0xffffffffu, accLo[0][w], 2 * k + 1);
        const uint32_t a1 = __shfl_sync(0xffffffffu, accLo[1][w], 2 * k + 1);
        vLo[4 + w] = hi ? a1 : a0;
        const uint32_t b0 = __shfl_sync(0xffffffffu, accHi[0][w], 2 * k + 1);
        const uint32_t b1 = __shfl_sync(0xffffffffu, accHi[1][w], 2 * k + 1);
        vHi[4 + w] = hi ? b1 : b0;
    }

    if (!FINAL) {
#pragma unroll
        for (int i = 0; i < 6; ++i) {
            __stcs(&g_P[(size_t)i * G3 + vox], vLo[i]);
            __stcs(&g_P[(size_t)(i + 6) * G3 + vox], vHi[i]);
        }
    } else {
#pragma unroll
        for (int i = 0; i < 6; ++i) {
            vLo[i] += __ldcs(&g_P[(size_t)i * G3 + vox]);
            vHi[i] += __ldcs(&g_P[(size_t)(i + 6) * G3 + vox]);
        }
        const float scale = 1.0f / (12.0f * 255.0f);
        float* outb = out + ((size_t)b * NJ) * G3 + vox;
#pragma unroll
        for (int w = 0; w < 6; ++w) {
            const int j0 = 4 * w;
            __stcs(&outb[(size_t)(j0 + 0) * G3], (float)(vLo[w] & 0xFFFFu) * scale);
            if (j0 + 1 < NJ) __stcs(&outb[(size_t)(j0 + 1) * G3], (float)(vHi[w] & 0xFFFFu) * scale);
            if (j0 + 2 < NJ) __stcs(&outb[(size_t)(j0 + 2) * G3], (float)(vLo[w] >> 16) * scale);
            if (j0 + 3 < NJ) __stcs(&outb[(size_t)(j0 + 3) * G3], (float)(vHi[w] >> 16) * scale);
        }
    }
}

extern "C" void kernel_launch(void* const* d_in, const int* in_sizes, int n_in,
                              void* d_out, int out_size)
{
    const float* heatmaps = (const float*)d_in[0];
    const float* center   = (const float*)d_in[1];
    const int2*  lookup   = (const int2*)d_in[2];
    float* out = (float*)d_out;

    // Created once on the first (uncaptured correctness) call; reused in capture.
    static cudaStream_t s_aux = []() {
        cudaStream_t s; cudaStreamCreateWithFlags(&s, cudaStreamNonBlocking); return s;
    }();
    static cudaEvent_t evT0 = []() {
        cudaEvent_t e; cudaEventCreateWithFlags(&e, cudaEventDisableTiming); return e;
    }();
    static cudaEvent_t evT1 = []() {
        cudaEvent_t e; cudaEventCreateWithFlags(&e, cudaEventDisableTiming); return e;
    }();

    const dim3 tgrid(HW / 1024, NC);
    const int nblk = G3 / 256;

    // main: T(b0); aux: T(b1) overlapped with b0 gathers (DRAM has headroom now)
    transpose_kernel<<<tgrid, 256>>>(heatmaps, 0);
    cudaEventRecord(evT0, 0);
    cudaStreamWaitEvent(s_aux, evT0, 0);
    transpose_kernel<<<tgrid, 256, 0, s_aux>>>(heatmaps, 1);
    cudaEventRecord(evT1, s_aux);

    gather_pass<0><<<nblk, 256>>>(center, lookup, out, 0, 0);
    gather_pass<1><<<nblk, 256>>>(center, lookup, out, 0, NCP);

    cudaStreamWaitEvent(0, evT1, 0);
    gather_pass<0><<<nblk, 256>>>(center, lookup, out, 1, 0);
    gather_pass<1><<<nblk, 256>>>(center, lookup, out, 1, NCP);
}

// round 15
// speedup vs baseline: 1.1918x; 1.0642x over previous
#include <cuda_runtime.h>
#include <cstdint>

// ReprojectionLayer: out[b,j,x,y,z] = mean_c heatmaps[b,c,j, v*512+u]
//   (u,v) = reproLookup[c, sx+x, sy+y, sz+z, :], s* = clamp(trunc((center+160)/2)-52, 0, L-G)
//
// Strategy (r14):
//   Pass 1: register-only transpose+quantize fp32 -> u8 rows (one 32B sector
//           per row), split into FOUR (batch, 6-cam half) launches.
//   Pass 2: FOUR gather passes (batch x 6-cam half, 50MB L2-resident WS),
//           pair-lane row fetch + shuffle reassembly, packed-u16 partials,
//           streaming hints (r13 core, unchanged).
//   NEW: cam-half pipelining — only T(b0,h0) (~30us) sits on the critical
//        path; the other three transposes hide under the gathers via an aux
//        stream with per-dependency events.
// Precision: u8 quantization -> rel_err ~6.4e-4 < 1e-3 (measured r8-r13).

#define NB 2
#define NC 12
#define NCP 6
#define NJ 23
#define GG 104
#define HALFG 52
#define LL 160
#define HMW 512
#define HW (512 * 512)
#define G3 (GG * GG * GG)   // 1,124,864 = 4394 * 256

// T: 2*12*262144 rows * 32B = 151 MB
__device__ uint4 g_T[(size_t)NB * NC * HW * 2];
// Partial sums: 12 u32 planes (u16-lane SIMD words) = 54 MB, reused per batch
__device__ uint32_t g_P[12 * (size_t)G3];

// ---------------- Pass 1: transpose + fp32 -> u8 (register-only) ----------------
// grid = (HW/1024, NCP): one launch per (batch, cam half).
__global__ __launch_bounds__(256) void transpose_kernel(const float* __restrict__ hm,
                                                        int b, int cam0)
{
    const int c = cam0 + blockIdx.y;
    const int p = blockIdx.x * 1024 + threadIdx.x * 4;

    const float4* src = reinterpret_cast<const float4*>(
        hm + ((size_t)(b * NC + c) * NJ) * HW + p);

    uint32_t w[4][6];
#pragma unroll
    for (int k = 0; k < 4; ++k)
#pragma unroll
        for (int i = 0; i < 6; ++i) w[k][i] = 0;

#pragma unroll
    for (int j = 0; j < NJ; ++j) {
        const float4 f = __ldcs(src + (size_t)j * (HW / 4));   // streaming read
        const int word = j >> 2, sh = 8 * (j & 3);
        w[0][word] |= __float2uint_rn(f.x * 255.0f) << sh;
        w[1][word] |= __float2uint_rn(f.y * 255.0f) << sh;
        w[2][word] |= __float2uint_rn(f.z * 255.0f) << sh;
        w[3][word] |= __float2uint_rn(f.w * 255.0f) << sh;
    }

    uint4* dst = g_T + ((size_t)(b * NC + c) * HW + p) * 2;
#pragma unroll
    for (int k = 0; k < 4; ++k) {
        __stcs(&dst[2 * k],     make_uint4(w[k][0], w[k][1], w[k][2], w[k][3]));
        __stcs(&dst[2 * k + 1], make_uint4(w[k][4], w[k][5], 0u, 0u));
    }
}

// ---------------- Pass 2: gather over 6 cams, pair-lane fetch (r13) ----------------
// FINAL=0: write packed u16 partials; FINAL=1: add partials, unpack, write fp32.
template <int FINAL>
__global__ __launch_bounds__(256) void gather_pass(
    const float* __restrict__ center,
    const int2* __restrict__ lookup,
    float* __restrict__ out,
    int b, int cam0)
{
    const int lane = threadIdx.x & 31;
    const int vox = blockIdx.x * blockDim.x + threadIdx.x;   // grid covers G3 exactly

    const int z = vox % GG;
    const int t = vox / GG;
    const int y = t % GG;
    const int x = t / GG;

    int sx = (int)((center[b * 3 + 0] + 160.0f) * 0.5f) - HALFG;
    int sy = (int)((center[b * 3 + 1] + 160.0f) * 0.5f) - HALFG;
    int sz = (int)((center[b * 3 + 2] + 160.0f) * 0.5f) - HALFG;
    sx = min(max(sx, 0), LL - GG);
    sy = min(max(sy, 0), LL - GG);
    sz = min(max(sz, 0), LL - GG);

    const int lx = sx + x, ly = sy + y, lz = sz + z;

    int base2[NCP];
#pragma unroll
    for (int c = 0; c < NCP; ++c) {
        const int cc = cam0 + c;
        const int lidx = ((cc * LL + lx) * LL + ly) * LL + lz;
        const int2 uv = __ldcs(&lookup[lidx]);                 // streaming: no reuse
        base2[c] = ((b * NC + cc) * HW + (uv.y * HMW + uv.x)) * 2;
    }

    // Pair-lane: lanes 2r,2r+1 fetch the two 16B halves of row r's 32B sector.
    uint32_t accLo[2][4] = {{0,0,0,0},{0,0,0,0}};
    uint32_t accHi[2][4] = {{0,0,0,0},{0,0,0,0}};
    const int srcRow = lane >> 1;
    const int part = lane & 1;

#pragma unroll
    for (int c = 0; c < NCP; ++c) {
#pragma unroll
        for (int h = 0; h < 2; ++h) {
            const int rowbase = __shfl_sync(0xffffffffu, base2[c], (h << 4) + srcRow);
            const uint4 q = __ldg(&g_T[rowbase + part]);       // reuse-bearing: cache in L2
            accLo[h][0] += q.x & 0x00FF00FFu;  accHi[h][0] += (q.x >> 8) & 0x00FF00FFu;
            accLo[h][1] += q.y & 0x00FF00FFu;  accHi[h][1] += (q.y >> 8) & 0x00FF00FFu;
            accLo[h][2] += q.z & 0x00FF00FFu;  accHi[h][2] += (q.z >> 8) & 0x00FF00FFu;
            accLo[h][3] += q.w & 0x00FF00FFu;  accHi[h][3] += (q.w >> 8) & 0x00FF00FFu;
        }
    }

    // Reassemble this voxel's 12 SIMD words.
    const int k = lane & 15;
    const bool hi = lane >= 16;
    uint32_t vLo[6], vHi[6];
#pragma unroll
    for (int w = 0; w < 4; ++w) {
        const uint32_t a0 = __shfl_sync(0xffffffffu, accLo[0][w], 2 * k);
        const uint32_t a1 = __shfl_sync(0xffffffffu, accLo[1][w], 2 * k);
        vLo[w] = hi ? a1 : a0;
        const uint32_t b0 = __shfl_sync(0xffffffffu, accHi[0][w], 2 * k);
        const uint32_t b1 = __shfl_sync(0xffffffffu, accHi[1][w], 2 * k);
        vHi[w] = hi ? b1 : b0;
    }
#pragma unroll
    for (int w = 0; w < 2; ++w) {
        const uint32_t a0 = __shfl_sync(0xffffffffu, accLo[0][w], 2 * k + 1);
        const uint32_t a1 = __shfl_sync(0xffffffffu, accLo[1][w], 2 * k + 1);
        vLo[4 + w] = hi ? a1 : a0;
        const uint32_t b0 = __shfl_sync(0xffffffffu, accHi[0][w], 2 * k + 1);
        const uint32_t b1 = __shfl_sync(0xffffffffu, accHi[1][w], 2 * k + 1);
        vHi[4 + w] = hi ? b1 : b0;
    }

    if (!FINAL) {
#pragma unroll
        for (int i = 0; i < 6; ++i) {
            __stcs(&g_P[(size_t)i * G3 + vox], vLo[i]);
            __stcs(&g_P[(size_t)(i + 6) * G3 + vox], vHi[i]);
        }
    } else {
#pragma unroll
        for (int i = 0; i < 6; ++i) {
            vLo[i] += __ldcs(&g_P[(size_t)i * G3 + vox]);
            vHi[i] += __ldcs(&g_P[(size_t)(i + 6) * G3 + vox]);
        }
        const float scale = 1.0f / (12.0f * 255.0f);
        float* outb = out + ((size_t)b * NJ) * G3 + vox;
#pragma unroll
        for (int w = 0; w < 6; ++w) {
            const int j0 = 4 * w;
            __stcs(&outb[(size_t)(j0 + 0) * G3], (float)(vLo[w] & 0xFFFFu) * scale);
            if (j0 + 1 < NJ) __stcs(&outb[(size_t)(j0 + 1) * G3], (float)(vHi[w] & 0xFFFFu) * scale);
            if (j0 + 2 < NJ) __stcs(&outb[(size_t)(j0 + 2) * G3], (float)(vLo[w] >> 16) * scale);
            if (j0 + 3 < NJ) __stcs(&outb[(size_t)(j0 + 3) * G3], (float)(vHi[w] >> 16) * scale);
        }
    }
}

extern "C" void kernel_launch(void* const* d_in, const int* in_sizes, int n_in,
                              void* d_out, int out_size)
{
    const float* heatmaps = (const float*)d_in[0];
    const float* center   = (const float*)d_in[1];
    const int2*  lookup   = (const int2*)d_in[2];
    float* out = (float*)d_out;

    // Created once on the first (uncaptured correctness) call; reused in capture.
    static cudaStream_t s_aux = []() {
        cudaStream_t s; cudaStreamCreateWithFlags(&s, cudaStreamNonBlocking); return s;
    }();
    static cudaEvent_t ev0 = []() {
        cudaEvent_t e; cudaEventCreateWithFlags(&e, cudaEventDisableTiming); return e;
    }();
    static cudaEvent_t evB0h1 = []() {
        cudaEvent_t e; cudaEventCreateWithFlags(&e, cudaEventDisableTiming); return e;
    }();
    static cudaEvent_t evB1h0 = []() {
        cudaEvent_t e; cudaEventCreateWithFlags(&e, cudaEventDisableTiming); return e;
    }();
    static cudaEvent_t evB1h1 = []() {
        cudaEvent_t e; cudaEventCreateWithFlags(&e, cudaEventDisableTiming); return e;
    }();

    const dim3 tgrid(HW / 1024, NCP);
    const int nblk = G3 / 256;

    // Critical path: only T(b0,h0); remaining transposes hide under gathers.
    transpose_kernel<<<tgrid, 256>>>(heatmaps, 0, 0);
    cudaEventRecord(ev0, 0);

    cudaStreamWaitEvent(s_aux, ev0, 0);
    transpose_kernel<<<tgrid, 256, 0, s_aux>>>(heatmaps, 0, NCP);
    cudaEventRecord(evB0h1, s_aux);
    transpose_kernel<<<tgrid, 256, 0, s_aux>>>(heatmaps, 1, 0);
    cudaEventRecord(evB1h0, s_aux);
    transpose_kernel<<<tgrid, 256, 0, s_aux>>>(heatmaps, 1, NCP);
    cudaEventRecord(evB1h1, s_aux);

    gather_pass<0><<<nblk, 256>>>(center, lookup, out, 0, 0);
    cudaStreamWaitEvent(0, evB0h1, 0);
    gather_pass<1><<<nblk, 256>>>(center, lookup, out, 0, NCP);
    cudaStreamWaitEvent(0, evB1h0, 0);
    gather_pass<0><<<nblk, 256>>>(center, lookup, out, 1, 0);
    cudaStreamWaitEvent(0, evB1h1, 0);
    gather_pass<1><<<nblk, 256>>>(center, lookup, out, 1, NCP);
}